// round 2
// baseline (speedup 1.0000x reference)
#include <cuda_runtime.h>

#define BATCH 32
#define SEQ   768
#define CDIM  256
#define HDIM  64
#define ROWS  (BATCH * SEQ)      // 24576
#define QTILES (SEQ / 64)        // 12

typedef unsigned long long u64;

// Scratch for projected Q, K, V (no cudaMalloc allowed)
__device__ float g_q[ROWS * HDIM];
__device__ float g_k[ROWS * HDIM];
__device__ float g_v[ROWS * HDIM];

// ---------------------------------------------------------------------------
// packed fp32x2 helpers (sm_100+ PTX)
// ---------------------------------------------------------------------------
__device__ __forceinline__ u64 pack2(float lo, float hi) {
    u64 r; asm("mov.b64 %0, {%1,%2};" : "=l"(r) : "f"(lo), "f"(hi)); return r;
}
__device__ __forceinline__ void unpack2(u64 v, float& lo, float& hi) {
    asm("mov.b64 {%0,%1}, %2;" : "=f"(lo), "=f"(hi) : "l"(v));
}
__device__ __forceinline__ u64 fma2(u64 a, u64 b, u64 c) {
    u64 d; asm("fma.rn.f32x2 %0, %1, %2, %3;" : "=l"(d) : "l"(a), "l"(b), "l"(c)); return d;
}
__device__ __forceinline__ u64 mul2(u64 a, u64 b) {
    u64 d; asm("mul.rn.f32x2 %0, %1, %2;" : "=l"(d) : "l"(a), "l"(b)); return d;
}

#define DUP_STRIDE 140   // floats; duplicated ("(v,v)") operand buffers
#define B_STRIDE   68    // floats; normal b-operand buffers

// ---------------------------------------------------------------------------
// Kernel 1: fused QKV projection on f32x2.
// Grid: ROWS/64 = 384 CTAs, 256 threads. Each CTA: 64 rows x (3 x 64) outputs.
// smem: xs_dup[64][140] (x^T, duplicated) + ws[3*64][68] = 88064 B.
// ---------------------------------------------------------------------------
__global__ __launch_bounds__(256, 2) void qkv_kernel(
    const float* __restrict__ x,
    const float* __restrict__ wq,
    const float* __restrict__ wk,
    const float* __restrict__ wv)
{
    extern __shared__ float sm[];
    float (*xs)[DUP_STRIDE] = (float(*)[DUP_STRIDE])sm;               // xs[c][2r(+1)] = x[r][c] dup
    float (*ws)[B_STRIDE]   = (float(*)[B_STRIDE])(sm + 64 * DUP_STRIDE); // ws[w*64+k][h]

    const int r0 = blockIdx.x * 64;
    const int t  = threadIdx.x;
    const int tr = t >> 4;     // 0..15
    const int tc = t & 15;     // 0..15

    u64 acc[3][4][2];
    #pragma unroll
    for (int w = 0; w < 3; w++)
        #pragma unroll
        for (int i = 0; i < 4; i++)
            #pragma unroll
            for (int j = 0; j < 2; j++) acc[w][i][j] = 0ull;

    // prefetch x chunk 0 into registers
    float4 xr[4];
    #pragma unroll
    for (int rep = 0; rep < 4; rep++) {
        int idx = t + rep * 256;
        int r = idx >> 4, c4 = (idx & 15) * 4;
        xr[rep] = *(const float4*)&x[(size_t)(r0 + r) * CDIM + c4];
    }

    for (int ch = 0; ch < 4; ch++) {
        __syncthreads();   // previous chunk's compute done with smem
        // store prefetched x chunk, duplicated+transposed
        #pragma unroll
        for (int rep = 0; rep < 4; rep++) {
            int idx = t + rep * 256;
            int r = idx >> 4, c4 = (idx & 15) * 4;
            float v[4] = {xr[rep].x, xr[rep].y, xr[rep].z, xr[rep].w};
            #pragma unroll
            for (int u = 0; u < 4; u++)
                *(u64*)&xs[c4 + u][2 * r] = pack2(v[u], v[u]);
        }
        // load weight chunks (L2-hot after first wave)
        {
            const float* wptr = wq;
            #pragma unroll
            for (int w = 0; w < 3; w++) {
                wptr = (w == 0) ? wq : (w == 1) ? wk : wv;
                #pragma unroll
                for (int rep = 0; rep < 4; rep++) {
                    int idx = t + rep * 256;
                    int k = idx >> 4, h4 = (idx & 15) * 4;
                    *(float4*)&ws[w * 64 + k][h4] =
                        *(const float4*)&wptr[(size_t)(ch * 64 + k) * HDIM + h4];
                }
            }
        }
        __syncthreads();
        // prefetch next x chunk (overlaps the GEMM below)
        if (ch < 3) {
            #pragma unroll
            for (int rep = 0; rep < 4; rep++) {
                int idx = t + rep * 256;
                int r = idx >> 4, c4 = (idx & 15) * 4;
                xr[rep] = *(const float4*)&x[(size_t)(r0 + r) * CDIM + (ch + 1) * 64 + c4];
            }
        }
        // GEMM: 24 FFMA2 per k
        #pragma unroll 8
        for (int k = 0; k < 64; k++) {
            ulonglong2 a01 = *(const ulonglong2*)&xs[k][tr * 8];
            ulonglong2 a23 = *(const ulonglong2*)&xs[k][tr * 8 + 4];
            u64 av[4] = {a01.x, a01.y, a23.x, a23.y};
            #pragma unroll
            for (int w = 0; w < 3; w++) {
                ulonglong2 b = *(const ulonglong2*)&ws[w * 64 + k][tc * 4];
                u64 bv[2] = {b.x, b.y};
                #pragma unroll
                for (int i = 0; i < 4; i++)
                    #pragma unroll
                    for (int j = 0; j < 2; j++)
                        acc[w][i][j] = fma2(av[i], bv[j], acc[w][i][j]);
            }
        }
    }

    // epilogue
    #pragma unroll
    for (int w = 0; w < 3; w++) {
        float* optr = (w == 0) ? g_q : (w == 1) ? g_k : g_v;
        #pragma unroll
        for (int i = 0; i < 4; i++) {
            float c0, c1, c2, c3;
            unpack2(acc[w][i][0], c0, c1);
            unpack2(acc[w][i][1], c2, c3);
            *(float4*)&optr[(size_t)(r0 + tr * 4 + i) * HDIM + tc * 4] =
                make_float4(c0, c1, c2, c3);
        }
    }
}

// ---------------------------------------------------------------------------
// Kernel 2: causal flash attention on f32x2, register-prefetched K/V pipeline.
// Grid: (12, 32). Block 256. smem: qs_dup + ks + vs + ps_dup = 106496 B.
// ---------------------------------------------------------------------------
__global__ __launch_bounds__(256, 2) void attn_kernel(float* __restrict__ out)
{
    extern __shared__ float sm[];
    float (*qs)[DUP_STRIDE] = (float(*)[DUP_STRIDE])sm;                       // qs[h][2i] (scaled, dup)
    float (*ks)[B_STRIDE]   = (float(*)[B_STRIDE])(sm + 64 * DUP_STRIDE);     // ks[h][j]  (K^T)
    float (*vs)[B_STRIDE]   = (float(*)[B_STRIDE])(sm + 64 * DUP_STRIDE + 64 * B_STRIDE); // vs[j][h]
    float (*ps)[DUP_STRIDE] = (float(*)[DUP_STRIDE])(sm + 64 * DUP_STRIDE + 2 * 64 * B_STRIDE); // ps[j][2i] (dup)

    const int qi = blockIdx.x;
    const int b  = blockIdx.y;
    const int q0 = qi * 64;
    const int t  = threadIdx.x;
    const int tr = t >> 4;
    const int tc = t & 15;
    const float scale = 0.125f;   // 1/sqrt(64), folded into Q

    // load Q tile: transposed, scaled, duplicated
    #pragma unroll
    for (int rep = 0; rep < 4; rep++) {
        int idx = t + rep * 256;
        int r = idx >> 4, h4 = (idx & 15) * 4;
        float4 qv = *(const float4*)&g_q[(size_t)(b * SEQ + q0 + r) * HDIM + h4];
        float v[4] = {qv.x * scale, qv.y * scale, qv.z * scale, qv.w * scale};
        #pragma unroll
        for (int u = 0; u < 4; u++)
            *(u64*)&qs[h4 + u][2 * r] = pack2(v[u], v[u]);
    }

    // prefetch K/V tile 0 into registers
    float4 kr[4], vr[4];
    {
        const size_t kbase = (size_t)(b * SEQ) * HDIM;
        #pragma unroll
        for (int rep = 0; rep < 4; rep++) {
            int idx = t + rep * 256;
            int j = idx >> 4, h4 = (idx & 15) * 4;
            kr[rep] = *(const float4*)&g_k[kbase + (size_t)j * HDIM + h4];
            vr[rep] = *(const float4*)&g_v[kbase + (size_t)j * HDIM + h4];
        }
    }

    u64 o2[4][2];
    #pragma unroll
    for (int i = 0; i < 4; i++) { o2[i][0] = 0ull; o2[i][1] = 0ull; }
    float m[4], l[4];
    #pragma unroll
    for (int i = 0; i < 4; i++) { m[i] = -1e30f; l[i] = 0.0f; }

    for (int kt = 0; kt <= qi; kt++) {
        __syncthreads();   // prev PV done with vs/ps; first iter: qs writes done

        // commit prefetched K (transposed) and V (natural)
        #pragma unroll
        for (int rep = 0; rep < 4; rep++) {
            int idx = t + rep * 256;
            int j = idx >> 4, h4 = (idx & 15) * 4;
            float kv[4] = {kr[rep].x, kr[rep].y, kr[rep].z, kr[rep].w};
            #pragma unroll
            for (int u = 0; u < 4; u++) ks[h4 + u][j] = kv[u];
            *(float4*)&vs[j][h4] = vr[rep];
        }
        __syncthreads();

        // prefetch next tile (overlaps S GEMM + softmax + PV)
        if (kt < qi) {
            const size_t nbase = (size_t)(b * SEQ + (kt + 1) * 64) * HDIM;
            #pragma unroll
            for (int rep = 0; rep < 4; rep++) {
                int idx = t + rep * 256;
                int j = idx >> 4, h4 = (idx & 15) * 4;
                kr[rep] = *(const float4*)&g_k[nbase + (size_t)j * HDIM + h4];
                vr[rep] = *(const float4*)&g_v[nbase + (size_t)j * HDIM + h4];
            }
        }

        // S = (Q*scale) K^T  -- 8 FFMA2 per h
        u64 s2[4][2];
        #pragma unroll
        for (int i = 0; i < 4; i++) { s2[i][0] = 0ull; s2[i][1] = 0ull; }
        #pragma unroll 8
        for (int h = 0; h < 64; h++) {
            ulonglong2 a01 = *(const ulonglong2*)&qs[h][tr * 8];
            ulonglong2 a23 = *(const ulonglong2*)&qs[h][tr * 8 + 4];
            u64 av[4] = {a01.x, a01.y, a23.x, a23.y};
            ulonglong2 bb = *(const ulonglong2*)&ks[h][tc * 4];
            u64 bv[2] = {bb.x, bb.y};
            #pragma unroll
            for (int i = 0; i < 4; i++)
                #pragma unroll
                for (int j = 0; j < 2; j++)
                    s2[i][j] = fma2(av[i], bv[j], s2[i][j]);
        }

        // unpack scores
        float s[4][4];
        #pragma unroll
        for (int i = 0; i < 4; i++) {
            unpack2(s2[i][0], s[i][0], s[i][1]);
            unpack2(s2[i][1], s[i][2], s[i][3]);
        }

        // causal mask (diagonal tile only)
        if (kt == qi) {
            #pragma unroll
            for (int i = 0; i < 4; i++)
                #pragma unroll
                for (int j = 0; j < 4; j++)
                    if ((tc * 4 + j) > (tr * 4 + i)) s[i][j] = -1e30f;
        }

        // row max across the 16 tc-lanes
        float mt[4];
        #pragma unroll
        for (int i = 0; i < 4; i++)
            mt[i] = fmaxf(fmaxf(s[i][0], s[i][1]), fmaxf(s[i][2], s[i][3]));
        #pragma unroll
        for (int off = 1; off < 16; off <<= 1)
            #pragma unroll
            for (int i = 0; i < 4; i++)
                mt[i] = fmaxf(mt[i], __shfl_xor_sync(0xffffffffu, mt[i], off));

        float esc[4];
        #pragma unroll
        for (int i = 0; i < 4; i++) {
            float mn = fmaxf(m[i], mt[i]);
            esc[i] = __expf(m[i] - mn);
            m[i] = mn;
        }

        // p = exp(s - m) in place; row sums
        float rs[4] = {0.f, 0.f, 0.f, 0.f};
        #pragma unroll
        for (int i = 0; i < 4; i++)
            #pragma unroll
            for (int j = 0; j < 4; j++) {
                float pv = __expf(s[i][j] - m[i]);
                s[i][j] = pv;
                rs[i] += pv;
            }
        #pragma unroll
        for (int off = 1; off < 16; off <<= 1)
            #pragma unroll
            for (int i = 0; i < 4; i++)
                rs[i] += __shfl_xor_sync(0xffffffffu, rs[i], off);

        #pragma unroll
        for (int i = 0; i < 4; i++) {
            l[i] = l[i] * esc[i] + rs[i];
            u64 e2 = pack2(esc[i], esc[i]);
            o2[i][0] = mul2(o2[i][0], e2);
            o2[i][1] = mul2(o2[i][1], e2);
        }

        // stage P transposed + duplicated
        #pragma unroll
        for (int i = 0; i < 4; i++)
            #pragma unroll
            for (int j = 0; j < 4; j++)
                *(u64*)&ps[tc * 4 + j][2 * (tr * 4 + i)] = pack2(s[i][j], s[i][j]);
        __syncthreads();

        // O += P V  -- 8 FFMA2 per j
        #pragma unroll 8
        for (int j = 0; j < 64; j++) {
            ulonglong2 a01 = *(const ulonglong2*)&ps[j][tr * 8];
            ulonglong2 a23 = *(const ulonglong2*)&ps[j][tr * 8 + 4];
            u64 av[4] = {a01.x, a01.y, a23.x, a23.y};
            ulonglong2 bb = *(const ulonglong2*)&vs[j][tc * 4];
            u64 bv[2] = {bb.x, bb.y};
            #pragma unroll
            for (int i = 0; i < 4; i++)
                #pragma unroll
                for (int c = 0; c < 2; c++)
                    o2[i][c] = fma2(av[i], bv[c], o2[i][c]);
        }
    }

    // normalize + write
    #pragma unroll
    for (int i = 0; i < 4; i++) {
        float inv = 1.0f / l[i];
        float c0, c1, c2, c3;
        unpack2(o2[i][0], c0, c1);
        unpack2(o2[i][1], c2, c3);
        *(float4*)&out[(size_t)(b * SEQ + q0 + tr * 4 + i) * HDIM + tc * 4] =
            make_float4(c0 * inv, c1 * inv, c2 * inv, c3 * inv);
    }
}

// ---------------------------------------------------------------------------
extern "C" void kernel_launch(void* const* d_in, const int* in_sizes, int n_in,
                              void* d_out, int out_size)
{
    const float* x  = (const float*)d_in[0];
    const float* wq = (const float*)d_in[1];
    const float* wk = (const float*)d_in[2];
    const float* wv = (const float*)d_in[3];
    float* out = (float*)d_out;

    const int QKV_SMEM  = (64 * DUP_STRIDE + 3 * 64 * B_STRIDE) * (int)sizeof(float);   // 88064
    const int ATTN_SMEM = (2 * 64 * DUP_STRIDE + 2 * 64 * B_STRIDE) * (int)sizeof(float); // 106496

    cudaFuncSetAttribute(qkv_kernel,  cudaFuncAttributeMaxDynamicSharedMemorySize, QKV_SMEM);
    cudaFuncSetAttribute(attn_kernel, cudaFuncAttributeMaxDynamicSharedMemorySize, ATTN_SMEM);

    qkv_kernel<<<ROWS / 64, 256, QKV_SMEM>>>(x, wq, wk, wv);
    attn_kernel<<<dim3(QTILES, BATCH), 256, ATTN_SMEM>>>(out);
}